// round 16
// baseline (speedup 1.0000x reference)
#include <cuda_runtime.h>
#include <cuda_bf16.h>
#include <math.h>

#define D 64
#define K 64
#define EPSV 1e-8f
#define NBLK 888    // 148 SMs x 6 CTAs: exactly one resident wave at 40 regs

// Global accumulators: [0:64)=colsum, [64:128)=distsum, [128:192)=count,
// [192]=separation sum. Statically zero-initialized; the last-finishing block
// reads them, computes the outputs, and resets them for the next replay.
__device__ float g_acc[193];
__device__ unsigned int g_done;   // completion counter (reset each launch)

__global__ void __launch_bounds__(256, 6) cluster_main_kernel(
    const float* __restrict__ z,       // [B, 64]
    const float* __restrict__ a,       // [B, 64]
    const float* __restrict__ centers, // [64, 64]
    float* __restrict__ out,
    int B)
{
    __shared__ float sc[K * D];     // centers, 16 KB
    __shared__ float s_col[K];
    __shared__ float s_dist[K];
    __shared__ float s_cnt[K];
    __shared__ float red[256];
    __shared__ unsigned int s_rank;

    const int tid  = threadIdx.x;
    const int lane = tid & 31;

    for (int i = tid; i < K * D; i += 256) sc[i] = centers[i];

    // ---------- dedicated separation block (overlaps the streaming pass) ----------
    if (blockIdx.x == gridDim.x - 1) {
        __syncthreads();
        float part = 0.0f;
        for (int p = tid; p < K * K; p += 256) {
            const int i = p >> 6, j = p & 63;
            if (i != j) {
                const float4* ci = (const float4*)(sc + i * D);
                const float4* cj = (const float4*)(sc + j * D);
                float s = 0.0f;
                #pragma unroll
                for (int t = 0; t < 16; t++) {
                    const int d4 = (t + lane) & 15;   // conflict-free rotation
                    const float4 x = ci[d4];
                    const float4 y = cj[d4];
                    float dx;
                    dx = x.x - y.x; s = fmaf(dx, dx, s);
                    dx = x.y - y.y; s = fmaf(dx, dx, s);
                    dx = x.z - y.z; s = fmaf(dx, dx, s);
                    dx = x.w - y.w; s = fmaf(dx, dx, s);
                }
                part += (s > 0.0f) ? sqrtf(s) : 0.0f;
            }
        }
        red[tid] = part;
        __syncthreads();
        for (int off = 128; off > 0; off >>= 1) {
            if (tid < off) red[tid] += red[tid + off];
            __syncthreads();
        }
        if (tid == 0) g_acc[192] = red[0];   // single writer
    } else {
        // ---------- streaming blocks ----------
        if (tid < K) { s_col[tid] = 0.0f; s_dist[tid] = 0.0f; s_cnt[tid] = 0.0f; }
        __syncthreads();

        const int warp = tid >> 5;
        const int sub  = lane >> 3;        // row within a 4-row group
        const int sl   = lane & 7;         // lane within subwarp
        const int cb0 = sl * 4;            // owned columns [cb0, cb0+4)
        const int cb1 = 32 + sl * 4;       // and [cb1, cb1+4)

        const int nstream = NBLK - 1;      // 887 streaming blocks
        const int gwarp   = blockIdx.x * 8 + warp;
        const int stride  = nstream * 8 * 8;

        float c0=0,c1=0,c2=0,c3=0,c4=0,c5=0,c6=0,c7=0;

        for (int base = gwarp * 8; base < B; base += stride) {
            const int rowA = base + sub;
            const int rowB = base + 4 + sub;
            const bool vA = (rowA < B);
            const bool vB = (rowB < B);
            const int offA = (vA ? rowA : (B - 1)) * D;
            const int offB = (vB ? rowB : (B - 1)) * D;

            // phase 1: a-loads for both groups + z-loads for group A
            const float4 aA0 = __ldcs((const float4*)(a + offA + cb0));
            const float4 aA1 = __ldcs((const float4*)(a + offA + cb1));
            const float4 aB0 = __ldcs((const float4*)(a + offB + cb0));
            const float4 aB1 = __ldcs((const float4*)(a + offB + cb1));
            const float4 zA0 = __ldcs((const float4*)(z + offA + cb0));
            const float4 zA1 = __ldcs((const float4*)(z + offA + cb1));

            // consume a-values: colsums + both argmax keys (frees 16 regs)
            if (vA) {
                c0 += aA0.x; c1 += aA0.y; c2 += aA0.z; c3 += aA0.w;
                c4 += aA1.x; c5 += aA1.y; c6 += aA1.z; c7 += aA1.w;
            }
            if (vB) {
                c0 += aB0.x; c1 += aB0.y; c2 += aB0.z; c3 += aB0.w;
                c4 += aB1.x; c5 += aB1.y; c6 += aB1.z; c7 += aB1.w;
            }

            int bestA;
            {
                float bv = aA0.x; int bi = cb0;
                if (aA0.y > bv) { bv = aA0.y; bi = cb0 + 1; }
                if (aA0.z > bv) { bv = aA0.z; bi = cb0 + 2; }
                if (aA0.w > bv) { bv = aA0.w; bi = cb0 + 3; }
                if (aA1.x > bv) { bv = aA1.x; bi = cb1;     }
                if (aA1.y > bv) { bv = aA1.y; bi = cb1 + 1; }
                if (aA1.z > bv) { bv = aA1.z; bi = cb1 + 2; }
                if (aA1.w > bv) { bv = aA1.w; bi = cb1 + 3; }
                unsigned long long key =
                    ((unsigned long long)__float_as_uint(bv) << 32) |
                    (unsigned long long)(63 - bi);
                #pragma unroll
                for (int off = 4; off > 0; off >>= 1) {
                    unsigned long long ok = __shfl_xor_sync(0xffffffffu, key, off, 8);
                    if (ok > key) key = ok;
                }
                bestA = 63 - (int)(key & 0xffffffffull);
            }
            int bestB;
            {
                float bv = aB0.x; int bi = cb0;
                if (aB0.y > bv) { bv = aB0.y; bi = cb0 + 1; }
                if (aB0.z > bv) { bv = aB0.z; bi = cb0 + 2; }
                if (aB0.w > bv) { bv = aB0.w; bi = cb0 + 3; }
                if (aB1.x > bv) { bv = aB1.x; bi = cb1;     }
                if (aB1.y > bv) { bv = aB1.y; bi = cb1 + 1; }
                if (aB1.z > bv) { bv = aB1.z; bi = cb1 + 2; }
                if (aB1.w > bv) { bv = aB1.w; bi = cb1 + 3; }
                unsigned long long key =
                    ((unsigned long long)__float_as_uint(bv) << 32) |
                    (unsigned long long)(63 - bi);
                #pragma unroll
                for (int off = 4; off > 0; off >>= 1) {
                    unsigned long long ok = __shfl_xor_sync(0xffffffffu, key, off, 8);
                    if (ok > key) key = ok;
                }
                bestB = 63 - (int)(key & 0xffffffffull);
            }

            // phase 2: z-loads for group B overlap group-A distance compute
            const float4 zB0 = __ldcs((const float4*)(z + offB + cb0));
            const float4 zB1 = __ldcs((const float4*)(z + offB + cb1));

            // distance A
            {
                const float4 cc0 = *(const float4*)(sc + bestA * D + cb0);
                const float4 cc1 = *(const float4*)(sc + bestA * D + cb1);
                float s = 0.0f, dx;
                dx = zA0.x - cc0.x; s = fmaf(dx, dx, s);
                dx = zA0.y - cc0.y; s = fmaf(dx, dx, s);
                dx = zA0.z - cc0.z; s = fmaf(dx, dx, s);
                dx = zA0.w - cc0.w; s = fmaf(dx, dx, s);
                dx = zA1.x - cc1.x; s = fmaf(dx, dx, s);
                dx = zA1.y - cc1.y; s = fmaf(dx, dx, s);
                dx = zA1.z - cc1.z; s = fmaf(dx, dx, s);
                dx = zA1.w - cc1.w; s = fmaf(dx, dx, s);
                #pragma unroll
                for (int off = 4; off > 0; off >>= 1)
                    s += __shfl_xor_sync(0xffffffffu, s, off, 8);
                if (sl == 0 && vA) {
                    atomicAdd(&s_dist[bestA], sqrtf(s));
                    atomicAdd(&s_cnt[bestA], 1.0f);
                }
            }

            // distance B
            {
                const float4 cc0 = *(const float4*)(sc + bestB * D + cb0);
                const float4 cc1 = *(const float4*)(sc + bestB * D + cb1);
                float s = 0.0f, dx;
                dx = zB0.x - cc0.x; s = fmaf(dx, dx, s);
                dx = zB0.y - cc0.y; s = fmaf(dx, dx, s);
                dx = zB0.z - cc0.z; s = fmaf(dx, dx, s);
                dx = zB0.w - cc0.w; s = fmaf(dx, dx, s);
                dx = zB1.x - cc1.x; s = fmaf(dx, dx, s);
                dx = zB1.y - cc1.y; s = fmaf(dx, dx, s);
                dx = zB1.z - cc1.z; s = fmaf(dx, dx, s);
                dx = zB1.w - cc1.w; s = fmaf(dx, dx, s);
                #pragma unroll
                for (int off = 4; off > 0; off >>= 1)
                    s += __shfl_xor_sync(0xffffffffu, s, off, 8);
                if (sl == 0 && vB) {
                    atomicAdd(&s_dist[bestB], sqrtf(s));
                    atomicAdd(&s_cnt[bestB], 1.0f);
                }
            }
        }

        // fold register column sums into block-shared
        atomicAdd(&s_col[cb0 + 0], c0);
        atomicAdd(&s_col[cb0 + 1], c1);
        atomicAdd(&s_col[cb0 + 2], c2);
        atomicAdd(&s_col[cb0 + 3], c3);
        atomicAdd(&s_col[cb1 + 0], c4);
        atomicAdd(&s_col[cb1 + 1], c5);
        atomicAdd(&s_col[cb1 + 2], c6);
        atomicAdd(&s_col[cb1 + 3], c7);
        __syncthreads();

        // one global atomic per slot per block (192 spread addresses, cheap)
        if (tid < 192) {
            const float v = (tid < 64) ? s_col[tid]
                          : (tid < 128) ? s_dist[tid - 64]
                          : s_cnt[tid - 128];
            atomicAdd(&g_acc[tid], v);
        }
    }

    // ---------- last-finishing block computes the outputs ----------
    __threadfence();                       // make this block's g_acc writes visible
    if (tid == 0) s_rank = atomicAdd(&g_done, 1u);
    __syncthreads();
    if (s_rank != (unsigned int)(gridDim.x - 1)) return;

    __shared__ float slot[193];
    if (tid < 193) {
        slot[tid] = __ldcg(&g_acc[tid]);
        g_acc[tid] = 0.0f;
    }
    if (tid == 0) g_done = 0u;             // reset counter for next replay
    __syncthreads();

    if (tid < 32) {
        const float invB = 1.0f / (float)B;
        const float u = 1.0f / (float)K;
        const float logu = logf(u);

        const float p0 = slot[lane]      * invB;
        const float p1 = slot[lane + 32] * invB;
        float bal  = u * (logu - logf(p0 + EPSV))
                   + u * (logu - logf(p1 + EPSV));
        float msum = p0 + p1;

        const float cnt0 = slot[128 + lane];
        const float cnt1 = slot[160 + lane];
        float comp = 0.0f, nn = 0.0f;
        if (cnt0 > 0.0f) { comp += slot[64 + lane] / cnt0; nn += 1.0f; }
        if (cnt1 > 0.0f) { comp += slot[96 + lane] / cnt1; nn += 1.0f; }

        #pragma unroll
        for (int off = 16; off > 0; off >>= 1) {
            bal  += __shfl_xor_sync(0xffffffffu, bal,  off);
            msum += __shfl_xor_sync(0xffffffffu, msum, off);
            comp += __shfl_xor_sync(0xffffffffu, comp, off);
            nn   += __shfl_xor_sync(0xffffffffu, nn,   off);
        }
        const float mean = msum / (float)K;
        float var = (p0 - mean) * (p0 - mean) + (p1 - mean) * (p1 - mean);
        #pragma unroll
        for (int off = 16; off > 0; off >>= 1)
            var += __shfl_xor_sync(0xffffffffu, var, off);

        if (lane == 0) {
            const float sep = -slot[192] / (float)(K * (K - 1));
            const float cb  = sqrtf(var / (float)(K - 1));
            comp = comp / ((nn > 0.0f) ? nn : 1.0f);
            const float aux = 0.1f * bal + 0.1f * sep + 0.1f * comp;
            out[0] = aux;
            out[1] = bal;
            out[2] = sep;
            out[3] = comp;
            out[4] = cb;
        }
    }
}

extern "C" void kernel_launch(void* const* d_in, const int* in_sizes, int n_in,
                              void* d_out, int out_size)
{
    const float* latent_z = (const float*)d_in[0];
    const float* assigns  = (const float*)d_in[1];
    const float* centers  = (const float*)d_in[2];
    float* out = (float*)d_out;

    const int B = in_sizes[0] / D;

    cluster_main_kernel<<<NBLK, 256>>>(latent_z, assigns, centers, out, B);
}

// round 17
// speedup vs baseline: 1.1221x; 1.1221x over previous
#include <cuda_runtime.h>
#include <cuda_bf16.h>
#include <math.h>

#define D 64
#define K 64
#define EPSV 1e-8f
#define NBLK 592    // 148 SMs x 4 CTAs (64 regs): exactly one resident wave

// Global accumulators: [0:64)=colsum, [64:128)=distsum, [128:192)=count,
// [192]=separation sum. Statically zero-initialized; the last-finishing block
// reads them, computes the outputs, and resets them for the next replay.
__device__ float g_acc[193];
__device__ unsigned int g_done;   // completion counter (reset each launch)

__global__ void __launch_bounds__(256) cluster_main_kernel(
    const float* __restrict__ z,       // [B, 64]
    const float* __restrict__ a,       // [B, 64]
    const float* __restrict__ centers, // [64, 64]
    float* __restrict__ out,
    int B)
{
    __shared__ float sc[K * D];     // centers, 16 KB
    __shared__ float s_col[K];
    __shared__ float s_dist[K];
    __shared__ float s_cnt[K];
    __shared__ float red[256];
    __shared__ unsigned int s_rank;

    const int tid  = threadIdx.x;
    const int lane = tid & 31;

    for (int i = tid; i < K * D; i += 256) sc[i] = centers[i];

    // ---------- dedicated separation block (overlaps the streaming pass) ----------
    if (blockIdx.x == gridDim.x - 1) {
        __syncthreads();
        float part = 0.0f;
        for (int p = tid; p < K * K; p += 256) {
            const int i = p >> 6, j = p & 63;
            if (i != j) {
                const float4* ci = (const float4*)(sc + i * D);
                const float4* cj = (const float4*)(sc + j * D);
                float s = 0.0f;
                #pragma unroll
                for (int t = 0; t < 16; t++) {
                    const int d4 = (t + lane) & 15;   // conflict-free rotation
                    const float4 x = ci[d4];
                    const float4 y = cj[d4];
                    float dx;
                    dx = x.x - y.x; s = fmaf(dx, dx, s);
                    dx = x.y - y.y; s = fmaf(dx, dx, s);
                    dx = x.z - y.z; s = fmaf(dx, dx, s);
                    dx = x.w - y.w; s = fmaf(dx, dx, s);
                }
                part += (s > 0.0f) ? sqrtf(s) : 0.0f;
            }
        }
        red[tid] = part;
        __syncthreads();
        for (int off = 128; off > 0; off >>= 1) {
            if (tid < off) red[tid] += red[tid + off];
            __syncthreads();
        }
        if (tid == 0) g_acc[192] = red[0];   // single writer
    } else {
        // ---------- streaming blocks ----------
        if (tid < K) { s_col[tid] = 0.0f; s_dist[tid] = 0.0f; s_cnt[tid] = 0.0f; }
        __syncthreads();

        const int warp = tid >> 5;
        const int sub  = lane >> 3;        // row within a 4-row group
        const int sl   = lane & 7;         // lane within subwarp
        const int cb0 = sl * 4;            // owned columns [cb0, cb0+4)
        const int cb1 = 32 + sl * 4;       // and [cb1, cb1+4)

        const int nstream = NBLK - 1;      // 591 streaming blocks
        const int gwarp   = blockIdx.x * 8 + warp;
        const int stride  = nstream * 8 * 8;

        float c0=0,c1=0,c2=0,c3=0,c4=0,c5=0,c6=0,c7=0;

        for (int base = gwarp * 8; base < B; base += stride) {
            const int rowA = base + sub;
            const int rowB = base + 4 + sub;
            const bool vA = (rowA < B);
            const bool vB = (rowB < B);
            const int rA = vA ? rowA : (B - 1);
            const int rB = vB ? rowB : (B - 1);

            const float4 aA0 = __ldcs((const float4*)(a + rA * D + cb0));
            const float4 aA1 = __ldcs((const float4*)(a + rA * D + cb1));
            const float4 aB0 = __ldcs((const float4*)(a + rB * D + cb0));
            const float4 aB1 = __ldcs((const float4*)(a + rB * D + cb1));
            const float4 zA0 = __ldcs((const float4*)(z + rA * D + cb0));
            const float4 zA1 = __ldcs((const float4*)(z + rA * D + cb1));
            const float4 zB0 = __ldcs((const float4*)(z + rB * D + cb0));
            const float4 zB1 = __ldcs((const float4*)(z + rB * D + cb1));

            // ---- group A ----
            if (vA) {
                c0 += aA0.x; c1 += aA0.y; c2 += aA0.z; c3 += aA0.w;
                c4 += aA1.x; c5 += aA1.y; c6 += aA1.z; c7 += aA1.w;
            }
            {
                float bv = aA0.x; int bi = cb0;
                if (aA0.y > bv) { bv = aA0.y; bi = cb0 + 1; }
                if (aA0.z > bv) { bv = aA0.z; bi = cb0 + 2; }
                if (aA0.w > bv) { bv = aA0.w; bi = cb0 + 3; }
                if (aA1.x > bv) { bv = aA1.x; bi = cb1;     }
                if (aA1.y > bv) { bv = aA1.y; bi = cb1 + 1; }
                if (aA1.z > bv) { bv = aA1.z; bi = cb1 + 2; }
                if (aA1.w > bv) { bv = aA1.w; bi = cb1 + 3; }
                unsigned long long key =
                    ((unsigned long long)__float_as_uint(bv) << 32) |
                    (unsigned long long)(63 - bi);
                #pragma unroll
                for (int off = 4; off > 0; off >>= 1) {
                    unsigned long long ok = __shfl_xor_sync(0xffffffffu, key, off, 8);
                    if (ok > key) key = ok;
                }
                const int best = 63 - (int)(key & 0xffffffffull);

                const float4 cc0 = *(const float4*)(sc + best * D + cb0);
                const float4 cc1 = *(const float4*)(sc + best * D + cb1);
                float s = 0.0f, dx;
                dx = zA0.x - cc0.x; s = fmaf(dx, dx, s);
                dx = zA0.y - cc0.y; s = fmaf(dx, dx, s);
                dx = zA0.z - cc0.z; s = fmaf(dx, dx, s);
                dx = zA0.w - cc0.w; s = fmaf(dx, dx, s);
                dx = zA1.x - cc1.x; s = fmaf(dx, dx, s);
                dx = zA1.y - cc1.y; s = fmaf(dx, dx, s);
                dx = zA1.z - cc1.z; s = fmaf(dx, dx, s);
                dx = zA1.w - cc1.w; s = fmaf(dx, dx, s);
                #pragma unroll
                for (int off = 4; off > 0; off >>= 1)
                    s += __shfl_xor_sync(0xffffffffu, s, off, 8);
                if (sl == 0 && vA) {
                    atomicAdd(&s_dist[best], sqrtf(s));
                    atomicAdd(&s_cnt[best], 1.0f);
                }
            }

            // ---- group B ----
            if (vB) {
                c0 += aB0.x; c1 += aB0.y; c2 += aB0.z; c3 += aB0.w;
                c4 += aB1.x; c5 += aB1.y; c6 += aB1.z; c7 += aB1.w;
            }
            {
                float bv = aB0.x; int bi = cb0;
                if (aB0.y > bv) { bv = aB0.y; bi = cb0 + 1; }
                if (aB0.z > bv) { bv = aB0.z; bi = cb0 + 2; }
                if (aB0.w > bv) { bv = aB0.w; bi = cb0 + 3; }
                if (aB1.x > bv) { bv = aB1.x; bi = cb1;     }
                if (aB1.y > bv) { bv = aB1.y; bi = cb1 + 1; }
                if (aB1.z > bv) { bv = aB1.z; bi = cb1 + 2; }
                if (aB1.w > bv) { bv = aB1.w; bi = cb1 + 3; }
                unsigned long long key =
                    ((unsigned long long)__float_as_uint(bv) << 32) |
                    (unsigned long long)(63 - bi);
                #pragma unroll
                for (int off = 4; off > 0; off >>= 1) {
                    unsigned long long ok = __shfl_xor_sync(0xffffffffu, key, off, 8);
                    if (ok > key) key = ok;
                }
                const int best = 63 - (int)(key & 0xffffffffull);

                const float4 cc0 = *(const float4*)(sc + best * D + cb0);
                const float4 cc1 = *(const float4*)(sc + best * D + cb1);
                float s = 0.0f, dx;
                dx = zB0.x - cc0.x; s = fmaf(dx, dx, s);
                dx = zB0.y - cc0.y; s = fmaf(dx, dx, s);
                dx = zB0.z - cc0.z; s = fmaf(dx, dx, s);
                dx = zB0.w - cc0.w; s = fmaf(dx, dx, s);
                dx = zB1.x - cc1.x; s = fmaf(dx, dx, s);
                dx = zB1.y - cc1.y; s = fmaf(dx, dx, s);
                dx = zB1.z - cc1.z; s = fmaf(dx, dx, s);
                dx = zB1.w - cc1.w; s = fmaf(dx, dx, s);
                #pragma unroll
                for (int off = 4; off > 0; off >>= 1)
                    s += __shfl_xor_sync(0xffffffffu, s, off, 8);
                if (sl == 0 && vB) {
                    atomicAdd(&s_dist[best], sqrtf(s));
                    atomicAdd(&s_cnt[best], 1.0f);
                }
            }
        }

        // fold register column sums into block-shared
        atomicAdd(&s_col[cb0 + 0], c0);
        atomicAdd(&s_col[cb0 + 1], c1);
        atomicAdd(&s_col[cb0 + 2], c2);
        atomicAdd(&s_col[cb0 + 3], c3);
        atomicAdd(&s_col[cb1 + 0], c4);
        atomicAdd(&s_col[cb1 + 1], c5);
        atomicAdd(&s_col[cb1 + 2], c6);
        atomicAdd(&s_col[cb1 + 3], c7);
        __syncthreads();

        // one global atomic per slot per block (192 spread addresses, cheap)
        if (tid < 192) {
            const float v = (tid < 64) ? s_col[tid]
                          : (tid < 128) ? s_dist[tid - 64]
                          : s_cnt[tid - 128];
            atomicAdd(&g_acc[tid], v);
        }
    }

    // ---------- last-finishing block computes the outputs ----------
    __threadfence();                       // make this block's g_acc writes visible
    if (tid == 0) s_rank = atomicAdd(&g_done, 1u);
    __syncthreads();
    if (s_rank != (unsigned int)(gridDim.x - 1)) return;

    __shared__ float slot[193];
    if (tid < 193) {
        slot[tid] = __ldcg(&g_acc[tid]);
        g_acc[tid] = 0.0f;
    }
    if (tid == 0) g_done = 0u;             // reset counter for next replay
    __syncthreads();

    if (tid < 32) {
        const float invB = 1.0f / (float)B;
        const float u = 1.0f / (float)K;
        const float logu = logf(u);

        const float p0 = slot[lane]      * invB;
        const float p1 = slot[lane + 32] * invB;
        float bal  = u * (logu - logf(p0 + EPSV))
                   + u * (logu - logf(p1 + EPSV));
        float msum = p0 + p1;

        const float cnt0 = slot[128 + lane];
        const float cnt1 = slot[160 + lane];
        float comp = 0.0f, nn = 0.0f;
        if (cnt0 > 0.0f) { comp += slot[64 + lane] / cnt0; nn += 1.0f; }
        if (cnt1 > 0.0f) { comp += slot[96 + lane] / cnt1; nn += 1.0f; }

        #pragma unroll
        for (int off = 16; off > 0; off >>= 1) {
            bal  += __shfl_xor_sync(0xffffffffu, bal,  off);
            msum += __shfl_xor_sync(0xffffffffu, msum, off);
            comp += __shfl_xor_sync(0xffffffffu, comp, off);
            nn   += __shfl_xor_sync(0xffffffffu, nn,   off);
        }
        const float mean = msum / (float)K;
        float var = (p0 - mean) * (p0 - mean) + (p1 - mean) * (p1 - mean);
        #pragma unroll
        for (int off = 16; off > 0; off >>= 1)
            var += __shfl_xor_sync(0xffffffffu, var, off);

        if (lane == 0) {
            const float sep = -slot[192] / (float)(K * (K - 1));
            const float cb  = sqrtf(var / (float)(K - 1));
            comp = comp / ((nn > 0.0f) ? nn : 1.0f);
            const float aux = 0.1f * bal + 0.1f * sep + 0.1f * comp;
            out[0] = aux;
            out[1] = bal;
            out[2] = sep;
            out[3] = comp;
            out[4] = cb;
        }
    }
}

extern "C" void kernel_launch(void* const* d_in, const int* in_sizes, int n_in,
                              void* d_out, int out_size)
{
    const float* latent_z = (const float*)d_in[0];
    const float* assigns  = (const float*)d_in[1];
    const float* centers  = (const float*)d_in[2];
    float* out = (float*)d_out;

    const int B = in_sizes[0] / D;

    cluster_main_kernel<<<NBLK, 256>>>(latent_z, assigns, centers, out, B);
}